// round 8
// baseline (speedup 1.0000x reference)
#include <cuda_runtime.h>
#include <cuda_fp16.h>
#include <cuda_bf16.h>
#include <math.h>
#include <stdint.h>

#define NNODE 10000
#define NEDGE 320000
#define ETOT  (NEDGE + NNODE)
#define FIN   256
#define HH    8
#define CC    64
#define FOUT  512   /* HH*CC */
#define NEG   0.2f

// ---------------- static device scratch (no allocations allowed) ------------
__device__ __align__(16) __half g_hh[NNODE * FOUT];   // GEMM out fp16 (10.2MB)
__device__ float g_als[NNODE * HH];       // atomic-accumulated att dots
__device__ float g_ald[NNODE * HH];
__device__ int   g_cnt[NNODE];
__device__ int   g_offs[NNODE + 1];
__device__ int   g_cursor[NNODE];
__device__ int2  g_edge[ETOT];            // dst-sorted CSR: (src, log2w-bits)
// packed bf16x2 hi/lo operand mirrors (kpair-packed: low half = even k)
__device__ __align__(16) uint32_t g_axh[NNODE * 256]; // A hi (x, then x2)
__device__ __align__(16) uint32_t g_axl[NNODE * 256]; // A lo
__device__ __align__(16) uint32_t g_bh[FOUT * 256];   // B^T hi
__device__ __align__(16) uint32_t g_bl[FOUT * 256];   // B^T lo

// ---------------- CSR build -------------------------------------------------
__global__ void k_zero() {
    int i = blockIdx.x * blockDim.x + threadIdx.x;
    if (i < NNODE * HH) { g_als[i] = 0.f; g_ald[i] = 0.f; }
    if (i < NNODE) g_cnt[i] = 0;
}
__global__ void k_zero_att() {
    int i = blockIdx.x * blockDim.x + threadIdx.x;
    if (i < NNODE * HH) { g_als[i] = 0.f; g_ald[i] = 0.f; }
}
__global__ void k_hist(const int* __restrict__ ei) {
    int e = blockIdx.x * blockDim.x + threadIdx.x;
    if (e >= ETOT) return;
    int d = (e < NEDGE) ? ei[NEDGE + e] : (e - NEDGE);
    atomicAdd(&g_cnt[d], 1);
}
__global__ void k_scan() {
    __shared__ int sh[1024];
    int t = threadIdx.x;
    const int CH = (NNODE + 1023) / 1024;
    int base = t * CH;
    int s = 0;
    for (int i = 0; i < CH; i++) {
        int idx = base + i;
        if (idx < NNODE) s += g_cnt[idx];
    }
    sh[t] = s;
    __syncthreads();
    for (int off = 1; off < 1024; off <<= 1) {
        int v = (t >= off) ? sh[t - off] : 0;
        __syncthreads();
        sh[t] += v;
        __syncthreads();
    }
    int run = (t == 0) ? 0 : sh[t - 1];
    for (int i = 0; i < CH; i++) {
        int idx = base + i;
        if (idx < NNODE) {
            g_offs[idx]   = run;
            g_cursor[idx] = run;
            run += g_cnt[idx];
        }
    }
    if (t == 1023) g_offs[NNODE] = run;
}
__global__ void k_scatter(const int* __restrict__ ei, const float* __restrict__ ew) {
    int e = blockIdx.x * blockDim.x + threadIdx.x;
    if (e >= ETOT) return;
    int s, d; float lw;
    if (e < NEDGE) {
        s = ei[e]; d = ei[NEDGE + e];
        lw = log2f(ew[e]);
    } else {
        s = d = e - NEDGE;
        lw = 0.f;
    }
    int pos = atomicAdd(&g_cursor[d], 1);
    g_edge[pos] = make_int2(s, __float_as_int(lw));
}

// ---------------- operand pre-splitting -------------------------------------
__device__ __forceinline__ void pack_pair(float e, float o,
                                          uint32_t& H, uint32_t& L) {
    __nv_bfloat162 h = __floats2bfloat162_rn(e, o);     // .x (low) = even k
    float2 hf = __bfloat1622float2(h);
    __nv_bfloat162 l = __floats2bfloat162_rn(e - hf.x, o - hf.y);
    H = *(uint32_t*)&h;
    L = *(uint32_t*)&l;
}

// x[N,256] fp32 -> g_axh/g_axl packed [row][128 kpairs]
__global__ void k_asplit(const float* __restrict__ x) {
    int i = blockIdx.x * blockDim.x + threadIdx.x;
    if (i >= NNODE * 64) return;
    int row = i >> 6, q = i & 63;
    float4 v = *(const float4*)(x + (size_t)row * FIN + q * 4);
    uint32_t h0, l0, h1, l1;
    pack_pair(v.x, v.y, h0, l0);
    pack_pair(v.z, v.w, h1, l1);
    size_t o = (size_t)row * 128 + 2 * q;
    *(uint2*)(g_axh + o) = make_uint2(h0, h1);
    *(uint2*)(g_axl + o) = make_uint2(l0, l1);
}

// W[K,512] fp32 -> g_bh/g_bl packed [n][K/2 kpairs]
__global__ void k_bsplit(const float* __restrict__ W, int K) {
    __shared__ float sh[64][33];
    int n0 = blockIdx.x * 32;
    int k0 = blockIdx.y * 64;
    int tx = threadIdx.x, ty = threadIdx.y;
    for (int r = ty; r < 64; r += 8)
        sh[r][tx] = W[(size_t)(k0 + r) * FOUT + n0 + tx];
    __syncthreads();
    int Kp = K >> 1;
    for (int i = ty; i < 32; i += 8) {
        int n = n0 + i;
        uint32_t H, L;
        pack_pair(sh[2 * tx][i], sh[2 * tx + 1][i], H, L);
        g_bh[(size_t)n * Kp + (k0 >> 1) + tx] = H;
        g_bl[(size_t)n * Kp + (k0 >> 1) + tx] = L;
    }
}

// ---------------- 3xBF16 HMMA GEMM (pre-split operands) ---------------------
// C[M,512] = A @ B^T via mma.m16n8k16.bf16, 3 products (hiH, hiL, loH).
// A/B read from the __device__ globals (g_axh/g_axl/g_bh/g_bl) — device-side
// symbol access only (host-side symbol-as-arg was the round-7 bug).
__device__ __forceinline__ void mma_bf16(float c[4],
                                         uint32_t a0, uint32_t a1, uint32_t a2, uint32_t a3,
                                         uint32_t b0, uint32_t b1) {
    asm volatile(
        "mma.sync.aligned.m16n8k16.row.col.f32.bf16.bf16.f32 "
        "{%0,%1,%2,%3}, {%4,%5,%6,%7}, {%8,%9}, {%0,%1,%2,%3};"
        : "+f"(c[0]), "+f"(c[1]), "+f"(c[2]), "+f"(c[3])
        : "r"(a0), "r"(a1), "r"(a2), "r"(a3), "r"(b0), "r"(b1));
}

#define SPITCH 136   /* words; 136 mod 32 = 8 -> conflict-free frag LDS */

__global__ __launch_bounds__(256) void k_gemm_tc(
    const float* __restrict__ att_s, const float* __restrict__ att_d,
    int M, int Kp)   /* Kp = K/2 kpairs per row */
{
    __shared__ uint32_t AsH[2][8][SPITCH];
    __shared__ uint32_t AsL[2][8][SPITCH];
    __shared__ uint32_t BsH[2][8][SPITCH];
    __shared__ uint32_t BsL[2][8][SPITCH];

    int bm = blockIdx.y * 128;
    int bn = blockIdx.x * 128;
    int tid  = threadIdx.x;
    int lane = tid & 31;
    int warp = tid >> 5;
    int wm = (warp & 1) * 64;   // warp row offset in block tile
    int wn = (warp >> 1) * 32;  // warp col offset in block tile

    // gmem->smem mapping: row = tid&127 (A row / B col), kseg = 4-kpair half
    int row  = tid & 127;
    int kseg = (tid >> 7) * 4;   // 0 or 4
    int arow = bm + row;
    bool arow_ok = arow < M;
    const uint32_t* aHp = g_axh + (size_t)arow * Kp + kseg;
    const uint32_t* aLp = g_axl + (size_t)arow * Kp + kseg;
    const uint32_t* bHp = g_bh + (size_t)(bn + row) * Kp + kseg;
    const uint32_t* bLp = g_bl + (size_t)(bn + row) * Kp + kseg;

    float acc[4][4][4];
#pragma unroll
    for (int mi = 0; mi < 4; mi++)
#pragma unroll
        for (int ni = 0; ni < 4; ni++)
#pragma unroll
            for (int r = 0; r < 4; r++) acc[mi][ni][r] = 0.f;

    uint4 rah, ral, rbh, rbl;
    auto load_tile = [&](int kp0) {
        if (arow_ok) {
            rah = *(const uint4*)(aHp + kp0);
            ral = *(const uint4*)(aLp + kp0);
        } else {
            rah = make_uint4(0u, 0u, 0u, 0u);
            ral = rah;
        }
        rbh = *(const uint4*)(bHp + kp0);
        rbl = *(const uint4*)(bLp + kp0);
    };
    auto store_tile = [&](int buf) {
        AsH[buf][kseg + 0][row] = rah.x;  AsH[buf][kseg + 1][row] = rah.y;
        AsH[buf][kseg + 2][row] = rah.z;  AsH[buf][kseg + 3][row] = rah.w;
        AsL[buf][kseg + 0][row] = ral.x;  AsL[buf][kseg + 1][row] = ral.y;
        AsL[buf][kseg + 2][row] = ral.z;  AsL[buf][kseg + 3][row] = ral.w;
        BsH[buf][kseg + 0][row] = rbh.x;  BsH[buf][kseg + 1][row] = rbh.y;
        BsH[buf][kseg + 2][row] = rbh.z;  BsH[buf][kseg + 3][row] = rbh.w;
        BsL[buf][kseg + 0][row] = rbl.x;  BsL[buf][kseg + 1][row] = rbl.y;
        BsL[buf][kseg + 2][row] = rbl.z;  BsL[buf][kseg + 3][row] = rbl.w;
    };

    load_tile(0);
    store_tile(0);
    __syncthreads();

    int buf = 0;
    for (int kp0 = 0; kp0 < Kp; kp0 += 8) {
        bool has_next = (kp0 + 8) < Kp;
        if (has_next) load_tile(kp0 + 8);

        int fk = lane & 3;
        int fg = lane >> 2;
        uint32_t ah[4][4], al[4][4];
#pragma unroll
        for (int mi = 0; mi < 4; mi++) {
            int m0 = wm + mi * 16 + fg;
            ah[mi][0] = AsH[buf][fk][m0];      ah[mi][1] = AsH[buf][fk][m0 + 8];
            ah[mi][2] = AsH[buf][fk + 4][m0];  ah[mi][3] = AsH[buf][fk + 4][m0 + 8];
            al[mi][0] = AsL[buf][fk][m0];      al[mi][1] = AsL[buf][fk][m0 + 8];
            al[mi][2] = AsL[buf][fk + 4][m0];  al[mi][3] = AsL[buf][fk + 4][m0 + 8];
        }
        uint32_t bh[4][2], bl[4][2];
#pragma unroll
        for (int ni = 0; ni < 4; ni++) {
            int n0 = wn + ni * 8 + fg;
            bh[ni][0] = BsH[buf][fk][n0];      bh[ni][1] = BsH[buf][fk + 4][n0];
            bl[ni][0] = BsL[buf][fk][n0];      bl[ni][1] = BsL[buf][fk + 4][n0];
        }

#pragma unroll
        for (int mi = 0; mi < 4; mi++)
#pragma unroll
            for (int ni = 0; ni < 4; ni++) {
                mma_bf16(acc[mi][ni], ah[mi][0], ah[mi][1], ah[mi][2], ah[mi][3],
                         bh[ni][0], bh[ni][1]);
                mma_bf16(acc[mi][ni], ah[mi][0], ah[mi][1], ah[mi][2], ah[mi][3],
                         bl[ni][0], bl[ni][1]);
                mma_bf16(acc[mi][ni], al[mi][0], al[mi][1], al[mi][2], al[mi][3],
                         bh[ni][0], bh[ni][1]);
            }

        if (has_next) store_tile(buf ^ 1);
        __syncthreads();
        buf ^= 1;
    }

    // ---- epilogue: fp16 store + fused att dot products ----
    int fg = lane >> 2;
    int fk = lane & 3;
    int headg = (bn + wn) >> 6;   // warp's 32 cols lie in exactly one head

    float vsv[4][2], vdv[4][2];
#pragma unroll
    for (int ni = 0; ni < 4; ni++) {
        int c = bn + wn + ni * 8 + fk * 2;
        vsv[ni][0] = att_s[c]; vsv[ni][1] = att_s[c + 1];
        vdv[ni][0] = att_d[c]; vdv[ni][1] = att_d[c + 1];
    }

#pragma unroll
    for (int mi = 0; mi < 4; mi++) {
        int r0 = bm + wm + mi * 16 + fg;
        int r1 = r0 + 8;
        float s0 = 0.f, d0 = 0.f, s1 = 0.f, d1 = 0.f;
#pragma unroll
        for (int ni = 0; ni < 4; ni++) {
            int col = bn + wn + ni * 8 + fk * 2;
            __half2 h01 = __floats2half2_rn(acc[mi][ni][0], acc[mi][ni][1]);
            __half2 h23 = __floats2half2_rn(acc[mi][ni][2], acc[mi][ni][3]);
            if (r0 < M) *(__half2*)(g_hh + (size_t)r0 * FOUT + col) = h01;
            if (r1 < M) *(__half2*)(g_hh + (size_t)r1 * FOUT + col) = h23;
            s0 += acc[mi][ni][0] * vsv[ni][0] + acc[mi][ni][1] * vsv[ni][1];
            d0 += acc[mi][ni][0] * vdv[ni][0] + acc[mi][ni][1] * vdv[ni][1];
            s1 += acc[mi][ni][2] * vsv[ni][0] + acc[mi][ni][3] * vsv[ni][1];
            d1 += acc[mi][ni][2] * vdv[ni][0] + acc[mi][ni][3] * vdv[ni][1];
        }
#pragma unroll
        for (int off = 2; off; off >>= 1) {
            s0 += __shfl_xor_sync(0xffffffffu, s0, off);
            d0 += __shfl_xor_sync(0xffffffffu, d0, off);
            s1 += __shfl_xor_sync(0xffffffffu, s1, off);
            d1 += __shfl_xor_sync(0xffffffffu, d1, off);
        }
        if (fk == 0) {
            if (r0 < M) {
                atomicAdd(&g_als[r0 * HH + headg], s0);
                atomicAdd(&g_ald[r0 * HH + headg], d0);
            }
            if (r1 < M) {
                atomicAdd(&g_als[r1 * HH + headg], s1);
                atomicAdd(&g_ald[r1 * HH + headg], d1);
            }
        }
    }
}

// ------------- fused flash softmax + aggregation: warp = (node, head) -------
// Layer 1 (out_ext == null): writes x2 as packed bf16 hi/lo into g_axh/g_axl.
// Layer 2: writes fp32 d_out. Never touches g_als/g_ald (race avoided).
__global__ void k_fusedagg(const float* __restrict__ bias,
                           float* __restrict__ out_ext, int do_relu)
{
    int n = blockIdx.x;
    int w = threadIdx.x >> 5, lane = threadIdx.x & 31;
    int s0 = g_offs[n], s1 = g_offs[n + 1];

    float adw = g_ald[n * HH + w];
    float m = -1e30f, ssum = 0.f, accx = 0.f, accy = 0.f;

    for (int base = s0; base < s1; base += 32) {
        int idx = base + lane;
        bool valid = idx < s1;
        int2 e2 = valid ? g_edge[idx] : make_int2(0, 0);
        int mys = e2.x;
        float t = -1e30f;
        if (valid) {
            float a = g_als[mys * HH + w] + adw;
            a = (a > 0.f) ? a : NEG * a;   // leaky_relu
            t = a + __int_as_float(e2.y);
        }
        float cm = t;
#pragma unroll
        for (int o = 16; o; o >>= 1)
            cm = fmaxf(cm, __shfl_xor_sync(0xffffffffu, cm, o));
        float mnew = fmaxf(m, cm);
        float scale = __expf(m - mnew);
        ssum *= scale; accx *= scale; accy *= scale;
        m = mnew;

        float e = __expf(t - mnew);
        ssum += e;

        int cnt = min(32, s1 - base);
        for (int j = 0; j < cnt; j++) {
            int   s  = __shfl_sync(0xffffffffu, mys, j);
            float wv = __shfl_sync(0xffffffffu, e, j);
            float2 hv = __half22float2(
                *(const __half2*)(g_hh + (size_t)s * FOUT + w * CC + lane * 2));
            accx = fmaf(wv, hv.x, accx);
            accy = fmaf(wv, hv.y, accy);
        }
    }
#pragma unroll
    for (int o = 16; o; o >>= 1)
        ssum += __shfl_xor_sync(0xffffffffu, ssum, o);

    float r = 1.f / ssum;
    float2 b = *(const float2*)(bias + w * CC + lane * 2);
    float ox = fmaf(accx, r, b.x);
    float oy = fmaf(accy, r, b.y);
    if (do_relu) { ox = fmaxf(ox, 0.f); oy = fmaxf(oy, 0.f); }

    if (out_ext) {
        *(float2*)(out_ext + (size_t)n * FOUT + w * CC + lane * 2) =
            make_float2(ox, oy);
    } else {
        uint32_t H, L;
        pack_pair(ox, oy, H, L);
        size_t kp = (size_t)n * 256 + w * 32 + lane;
        g_axh[kp] = H;
        g_axl[kp] = L;
    }
}

// ---------------- launch -----------------------------------------------------
extern "C" void kernel_launch(void* const* d_in, const int* in_sizes, int n_in,
                              void* d_out, int out_size)
{
    const float* x   = (const float*)d_in[0];
    const int*   ei  = (const int*)  d_in[1];
    const float* ew  = (const float*)d_in[2];
    const float* W1  = (const float*)d_in[3];
    const float* as1 = (const float*)d_in[4];
    const float* ad1 = (const float*)d_in[5];
    const float* b1  = (const float*)d_in[6];
    const float* W2  = (const float*)d_in[7];
    const float* as2 = (const float*)d_in[8];
    const float* ad2 = (const float*)d_in[9];
    const float* b2  = (const float*)d_in[10];
    float* out = (float*)d_out;

    // CSR build + operand prep (shared by both layers)
    k_zero<<<(NNODE * HH + 255) / 256, 256>>>();
    k_hist<<<(ETOT + 255) / 256, 256>>>(ei);
    k_scan<<<1, 1024>>>();
    k_scatter<<<(ETOT + 255) / 256, 256>>>(ei, ew);
    k_asplit<<<(NNODE * 64 + 255) / 256, 256>>>(x);

    dim3 ggrid(FOUT / 128, (NNODE + 127) / 128);
    dim3 tblk(32, 8);

    // layer 1
    k_bsplit<<<dim3(FOUT / 32, FIN / 64), tblk>>>(W1, FIN);
    k_gemm_tc<<<ggrid, 256>>>(as1, ad1, NNODE, FIN / 2);
    k_fusedagg<<<NNODE, 256>>>(b1, nullptr, 1);   // -> packed x2 (bf16 hi/lo)

    k_zero_att<<<(NNODE * HH + 255) / 256, 256>>>();

    // layer 2
    k_bsplit<<<dim3(FOUT / 32, FOUT / 64), tblk>>>(W2, FOUT);
    k_gemm_tc<<<ggrid, 256>>>(as2, ad2, NNODE, FOUT / 2);
    k_fusedagg<<<NNODE, 256>>>(b2, out, 0);       // -> d_out fp32
}

// round 9
// speedup vs baseline: 1.3108x; 1.3108x over previous
#include <cuda_runtime.h>
#include <cuda_fp16.h>
#include <cuda_bf16.h>
#include <math.h>
#include <stdint.h>

#define NNODE 10000
#define NEDGE 320000
#define ETOT  (NEDGE + NNODE)
#define FIN   256
#define HH    8
#define CC    64
#define FOUT  512   /* HH*CC */
#define NEG   0.2f

// ---------------- static device scratch (no allocations allowed) ------------
__device__ __align__(16) __half g_hh[NNODE * FOUT];   // GEMM out fp16 (10.2MB)
__device__ float g_x2[NNODE * FOUT];      // layer-1 activated output (20.5 MB)
__device__ float g_als[2][NNODE * HH];    // att dots, one set per layer
__device__ float g_ald[2][NNODE * HH];
__device__ int   g_cnt[NNODE];
__device__ int   g_offs[NNODE + 1];
__device__ int   g_cursor[NNODE];
__device__ int2  g_edge[ETOT];            // dst-sorted CSR: (src, log2w-bits)

// ---------------- zero init (cnt + both layers' att accumulators) -----------
__global__ void k_zero() {
    int i = blockIdx.x * blockDim.x + threadIdx.x;
    if (i < NNODE * HH) {
        g_als[0][i] = 0.f; g_ald[0][i] = 0.f;
        g_als[1][i] = 0.f; g_ald[1][i] = 0.f;
    }
    if (i < NNODE) g_cnt[i] = 0;
}
__global__ void k_hist(const int* __restrict__ ei) {
    int e = blockIdx.x * blockDim.x + threadIdx.x;
    if (e >= ETOT) return;
    int d = (e < NEDGE) ? ei[NEDGE + e] : (e - NEDGE);
    atomicAdd(&g_cnt[d], 1);
}
__global__ void k_scan() {
    __shared__ int sh[1024];
    int t = threadIdx.x;
    const int CH = (NNODE + 1023) / 1024;
    int base = t * CH;
    int s = 0;
    for (int i = 0; i < CH; i++) {
        int idx = base + i;
        if (idx < NNODE) s += g_cnt[idx];
    }
    sh[t] = s;
    __syncthreads();
    for (int off = 1; off < 1024; off <<= 1) {
        int v = (t >= off) ? sh[t - off] : 0;
        __syncthreads();
        sh[t] += v;
        __syncthreads();
    }
    int run = (t == 0) ? 0 : sh[t - 1];
    for (int i = 0; i < CH; i++) {
        int idx = base + i;
        if (idx < NNODE) {
            g_offs[idx]   = run;
            g_cursor[idx] = run;
            run += g_cnt[idx];
        }
    }
    if (t == 1023) g_offs[NNODE] = run;
}
__global__ void k_scatter(const int* __restrict__ ei, const float* __restrict__ ew) {
    int e = blockIdx.x * blockDim.x + threadIdx.x;
    if (e >= ETOT) return;
    int s, d; float lw;
    if (e < NEDGE) {
        s = ei[e]; d = ei[NEDGE + e];
        lw = log2f(ew[e]);
    } else {
        s = d = e - NEDGE;
        lw = 0.f;
    }
    int pos = atomicAdd(&g_cursor[d], 1);
    g_edge[pos] = make_int2(s, __float_as_int(lw));
}

// ---------------- 3xBF16 tensor-core GEMM + fused att-dot epilogue ----------
// Round-5 proven form: coalesced fp32 loads, hi/lo split in registers,
// mma.m16n8k16.bf16 x3 products, double-buffered smem.
__device__ __forceinline__ uint32_t bf16x2(float odd, float even) {
    uint32_t r;
    asm("cvt.rn.bf16x2.f32 %0, %1, %2;" : "=r"(r) : "f"(odd), "f"(even));
    return r;
}
__device__ __forceinline__ void split2(float even, float odd,
                                       uint32_t& H, uint32_t& L) {
    H = bf16x2(odd, even);
    float eh = __uint_as_float(H << 16);
    float oh = __uint_as_float(H & 0xffff0000u);
    L = bf16x2(odd - oh, even - eh);
}
__device__ __forceinline__ void mma_bf16(float c[4],
                                         uint32_t a0, uint32_t a1, uint32_t a2, uint32_t a3,
                                         uint32_t b0, uint32_t b1) {
    asm volatile(
        "mma.sync.aligned.m16n8k16.row.col.f32.bf16.bf16.f32 "
        "{%0,%1,%2,%3}, {%4,%5,%6,%7}, {%8,%9}, {%0,%1,%2,%3};"
        : "+f"(c[0]), "+f"(c[1]), "+f"(c[2]), "+f"(c[3])
        : "r"(a0), "r"(a1), "r"(a2), "r"(a3), "r"(b0), "r"(b1));
}

#define SPITCH 136   /* words; 136 mod 32 = 8 -> conflict-free frag LDS */

__global__ __launch_bounds__(256) void k_gemm_tc(
    const float* __restrict__ A_ext, const float* __restrict__ B,
    const float* __restrict__ att_s, const float* __restrict__ att_d,
    int M, int K, int layer)
{
    __shared__ uint32_t AsH[2][8][SPITCH];
    __shared__ uint32_t AsL[2][8][SPITCH];
    __shared__ uint32_t BsH[2][8][SPITCH];
    __shared__ uint32_t BsL[2][8][SPITCH];

    const float* A = layer ? g_x2 : A_ext;
    float* als = g_als[layer];
    float* ald = g_ald[layer];
    const int NN = FOUT;

    int bm = blockIdx.y * 128;
    int bn = blockIdx.x * 128;
    int tid  = threadIdx.x;
    int lane = tid & 31;
    int warp = tid >> 5;
    int wm = (warp & 1) * 64;
    int wn = (warp >> 1) * 32;

    int am = tid >> 1;
    int ak = (tid & 1) * 8;
    int arow = bm + am;
    int br = tid >> 5;
    int bc = (tid & 31) * 4;

    float acc[4][4][4];
#pragma unroll
    for (int mi = 0; mi < 4; mi++)
#pragma unroll
        for (int ni = 0; ni < 4; ni++)
#pragma unroll
            for (int r = 0; r < 4; r++) acc[mi][ni][r] = 0.f;

    float4 a0v, a1v, b0v, b1v;
    auto load_tile = [&](int k0) {
        if (arow < M) {
            a0v = *(const float4*)(A + (size_t)arow * K + k0 + ak);
            a1v = *(const float4*)(A + (size_t)arow * K + k0 + ak + 4);
        } else {
            a0v = a1v = make_float4(0.f, 0.f, 0.f, 0.f);
        }
        b0v = *(const float4*)(B + (size_t)(k0 + 2 * br) * NN + bn + bc);
        b1v = *(const float4*)(B + (size_t)(k0 + 2 * br + 1) * NN + bn + bc);
    };
    auto store_tile = [&](int buf) {
        float va[8] = {a0v.x, a0v.y, a0v.z, a0v.w, a1v.x, a1v.y, a1v.z, a1v.w};
        int k2b = ak >> 1;
#pragma unroll
        for (int j = 0; j < 4; j++) {
            uint32_t H, L;
            split2(va[2 * j], va[2 * j + 1], H, L);
            AsH[buf][k2b + j][am] = H;
            AsL[buf][k2b + j][am] = L;
        }
        float ve[4] = {b0v.x, b0v.y, b0v.z, b0v.w};
        float vo[4] = {b1v.x, b1v.y, b1v.z, b1v.w};
        uint32_t BH[4], BL[4];
#pragma unroll
        for (int j = 0; j < 4; j++) split2(ve[j], vo[j], BH[j], BL[j]);
        *(uint4*)&BsH[buf][br][bc] = make_uint4(BH[0], BH[1], BH[2], BH[3]);
        *(uint4*)&BsL[buf][br][bc] = make_uint4(BL[0], BL[1], BL[2], BL[3]);
    };

    load_tile(0);
    store_tile(0);
    __syncthreads();

    int buf = 0;
    for (int k0 = 0; k0 < K; k0 += 16) {
        bool has_next = (k0 + 16) < K;
        if (has_next) load_tile(k0 + 16);

        int fk = lane & 3;
        int fg = lane >> 2;
        uint32_t ah[4][4], al[4][4];
#pragma unroll
        for (int mi = 0; mi < 4; mi++) {
            int m0 = wm + mi * 16 + fg;
            ah[mi][0] = AsH[buf][fk][m0];      ah[mi][1] = AsH[buf][fk][m0 + 8];
            ah[mi][2] = AsH[buf][fk + 4][m0];  ah[mi][3] = AsH[buf][fk + 4][m0 + 8];
            al[mi][0] = AsL[buf][fk][m0];      al[mi][1] = AsL[buf][fk][m0 + 8];
            al[mi][2] = AsL[buf][fk + 4][m0];  al[mi][3] = AsL[buf][fk + 4][m0 + 8];
        }
        uint32_t bh[4][2], bl[4][2];
#pragma unroll
        for (int ni = 0; ni < 4; ni++) {
            int n0 = wn + ni * 8 + fg;
            bh[ni][0] = BsH[buf][fk][n0];      bh[ni][1] = BsH[buf][fk + 4][n0];
            bl[ni][0] = BsL[buf][fk][n0];      bl[ni][1] = BsL[buf][fk + 4][n0];
        }

#pragma unroll
        for (int mi = 0; mi < 4; mi++)
#pragma unroll
            for (int ni = 0; ni < 4; ni++) {
                mma_bf16(acc[mi][ni], ah[mi][0], ah[mi][1], ah[mi][2], ah[mi][3],
                         bh[ni][0], bh[ni][1]);
                mma_bf16(acc[mi][ni], ah[mi][0], ah[mi][1], ah[mi][2], ah[mi][3],
                         bl[ni][0], bl[ni][1]);
                mma_bf16(acc[mi][ni], al[mi][0], al[mi][1], al[mi][2], al[mi][3],
                         bh[ni][0], bh[ni][1]);
            }

        if (has_next) store_tile(buf ^ 1);
        __syncthreads();
        buf ^= 1;
    }

    // ---- epilogue: fp16 store + fused att dot products ----
    int fg = lane >> 2;
    int fk = lane & 3;
    int headg = (bn + wn) >> 6;

    float vsv[4][2], vdv[4][2];
#pragma unroll
    for (int ni = 0; ni < 4; ni++) {
        int c = bn + wn + ni * 8 + fk * 2;
        vsv[ni][0] = att_s[c]; vsv[ni][1] = att_s[c + 1];
        vdv[ni][0] = att_d[c]; vdv[ni][1] = att_d[c + 1];
    }

#pragma unroll
    for (int mi = 0; mi < 4; mi++) {
        int r0 = bm + wm + mi * 16 + fg;
        int r1 = r0 + 8;
        float s0 = 0.f, d0 = 0.f, s1 = 0.f, d1 = 0.f;
#pragma unroll
        for (int ni = 0; ni < 4; ni++) {
            int col = bn + wn + ni * 8 + fk * 2;
            __half2 h01 = __floats2half2_rn(acc[mi][ni][0], acc[mi][ni][1]);
            __half2 h23 = __floats2half2_rn(acc[mi][ni][2], acc[mi][ni][3]);
            if (r0 < M) *(__half2*)(g_hh + (size_t)r0 * NN + col) = h01;
            if (r1 < M) *(__half2*)(g_hh + (size_t)r1 * NN + col) = h23;
            s0 += acc[mi][ni][0] * vsv[ni][0] + acc[mi][ni][1] * vsv[ni][1];
            d0 += acc[mi][ni][0] * vdv[ni][0] + acc[mi][ni][1] * vdv[ni][1];
            s1 += acc[mi][ni][2] * vsv[ni][0] + acc[mi][ni][3] * vsv[ni][1];
            d1 += acc[mi][ni][2] * vdv[ni][0] + acc[mi][ni][3] * vdv[ni][1];
        }
#pragma unroll
        for (int off = 2; off; off >>= 1) {
            s0 += __shfl_xor_sync(0xffffffffu, s0, off);
            d0 += __shfl_xor_sync(0xffffffffu, d0, off);
            s1 += __shfl_xor_sync(0xffffffffu, s1, off);
            d1 += __shfl_xor_sync(0xffffffffu, d1, off);
        }
        if (fk == 0) {
            if (r0 < M) {
                atomicAdd(&als[r0 * HH + headg], s0);
                atomicAdd(&ald[r0 * HH + headg], d0);
            }
            if (r1 < M) {
                atomicAdd(&als[r1 * HH + headg], s1);
                atomicAdd(&ald[r1 * HH + headg], d1);
            }
        }
    }
}

// ------------- fused flash softmax + aggregation: warp = (node, head) -------
// Unrolled-8 gather groups: 8 independent h-row loads in flight (MLP=8).
// Invalid j's read row 0 with weight 0 (L1-resident, harmless).
__global__ void k_fusedagg(const float* __restrict__ bias,
                           float* __restrict__ out_ext, int do_relu, int layer)
{
    int n = blockIdx.x;
    int w = threadIdx.x >> 5, lane = threadIdx.x & 31;
    float* out = out_ext ? out_ext : g_x2;
    const float* als = g_als[layer];
    int s0 = g_offs[n], s1 = g_offs[n + 1];

    float adw = g_ald[layer][n * HH + w];
    float m = -1e30f, ssum = 0.f, accx = 0.f, accy = 0.f;

    for (int base = s0; base < s1; base += 32) {
        int idx = base + lane;
        bool valid = idx < s1;
        int2 e2 = valid ? g_edge[idx] : make_int2(0, 0);
        int mys = e2.x;          // 0 for invalid lanes
        float t = -1e30f;
        if (valid) {
            float a = als[mys * HH + w] + adw;
            a = (a > 0.f) ? a : NEG * a;   // leaky_relu
            t = a + __int_as_float(e2.y);
        }
        float cm = t;
#pragma unroll
        for (int o = 16; o; o >>= 1)
            cm = fmaxf(cm, __shfl_xor_sync(0xffffffffu, cm, o));
        float mnew = fmaxf(m, cm);
        float scale = __expf(m - mnew);
        ssum *= scale; accx *= scale; accy *= scale;
        m = mnew;

        float e = __expf(t - mnew);   // exactly 0 for invalid lanes
        ssum += e;

        int cnt = min(32, s1 - base);
        const __half* hrow_base = g_hh + w * CC + lane * 2;
        for (int jb = 0; jb < cnt; jb += 8) {
            float wv[8];
            float2 hv[8];
#pragma unroll
            for (int u = 0; u < 8; u++) {
                int j = (jb + u) & 31;
                int   s  = __shfl_sync(0xffffffffu, mys, j);
                wv[u]    = __shfl_sync(0xffffffffu, e, j);
                hv[u] = __half22float2(
                    *(const __half2*)(hrow_base + (size_t)s * FOUT));
            }
#pragma unroll
            for (int u = 0; u < 8; u++) {
                accx = fmaf(wv[u], hv[u].x, accx);
                accy = fmaf(wv[u], hv[u].y, accy);
            }
        }
    }
#pragma unroll
    for (int o = 16; o; o >>= 1)
        ssum += __shfl_xor_sync(0xffffffffu, ssum, o);

    float r = 1.f / ssum;
    float2 b = *(const float2*)(bias + w * CC + lane * 2);
    float ox = fmaf(accx, r, b.x);
    float oy = fmaf(accy, r, b.y);
    if (do_relu) { ox = fmaxf(ox, 0.f); oy = fmaxf(oy, 0.f); }
    *(float2*)(out + (size_t)n * FOUT + w * CC + lane * 2) = make_float2(ox, oy);
}

// ---------------- launch -----------------------------------------------------
extern "C" void kernel_launch(void* const* d_in, const int* in_sizes, int n_in,
                              void* d_out, int out_size)
{
    const float* x   = (const float*)d_in[0];
    const int*   ei  = (const int*)  d_in[1];
    const float* ew  = (const float*)d_in[2];
    const float* W1  = (const float*)d_in[3];
    const float* as1 = (const float*)d_in[4];
    const float* ad1 = (const float*)d_in[5];
    const float* b1  = (const float*)d_in[6];
    const float* W2  = (const float*)d_in[7];
    const float* as2 = (const float*)d_in[8];
    const float* ad2 = (const float*)d_in[9];
    const float* b2  = (const float*)d_in[10];
    float* out = (float*)d_out;

    // CSR build + zero (shared by both layers)
    k_zero<<<(NNODE * HH + 255) / 256, 256>>>();
    k_hist<<<(ETOT + 255) / 256, 256>>>(ei);
    k_scan<<<1, 1024>>>();
    k_scatter<<<(ETOT + 255) / 256, 256>>>(ei, ew);

    dim3 ggrid(FOUT / 128, (NNODE + 127) / 128);

    // layer 1
    k_gemm_tc<<<ggrid, 256>>>(x, W1, as1, ad1, NNODE, FIN, 0);
    k_fusedagg<<<NNODE, 256>>>(b1, nullptr, 1, 0);    // -> g_x2 with ReLU

    // layer 2
    k_gemm_tc<<<ggrid, 256>>>(nullptr, W2, as2, ad2, NNODE, FOUT, 1);
    k_fusedagg<<<NNODE, 256>>>(b2, out, 0, 1);        // -> d_out, no ReLU
}

// round 10
// speedup vs baseline: 1.4124x; 1.0775x over previous
#include <cuda_runtime.h>
#include <cuda_fp16.h>
#include <cuda_bf16.h>
#include <math.h>
#include <stdint.h>

#define NNODE 10000
#define NEDGE 320000
#define ETOT  (NEDGE + NNODE)
#define FIN   256
#define HH    8
#define CC    64
#define FOUT  512   /* HH*CC */
#define NEG   0.2f

// ---------------- static device scratch (no allocations allowed) ------------
__device__ __align__(16) __half g_hh[NNODE * FOUT];   // GEMM out fp16 (10.2MB)
__device__ float g_x2[NNODE * FOUT];      // layer-1 activated output (20.5 MB)
__device__ float g_als[2][NNODE * HH];    // att dots, one set per layer
__device__ float g_ald[2][NNODE * HH];
__device__ int   g_cnt[NNODE];
__device__ int   g_offs[NNODE + 1];
__device__ int   g_cursor[NNODE];
__device__ int2  g_edge[ETOT];            // dst-sorted CSR: (src, log2w-bits)

// ---------------- zero kernels ----------------------------------------------
__global__ void k_zero_att() {
    int i = blockIdx.x * blockDim.x + threadIdx.x;
    if (i < NNODE * HH) {
        g_als[0][i] = 0.f; g_ald[0][i] = 0.f;
        g_als[1][i] = 0.f; g_ald[1][i] = 0.f;
    }
}
__global__ void k_zero_cnt() {
    int i = blockIdx.x * blockDim.x + threadIdx.x;
    if (i < NNODE) g_cnt[i] = 0;
}
__global__ void k_hist(const int* __restrict__ ei) {
    int e = blockIdx.x * blockDim.x + threadIdx.x;
    if (e >= ETOT) return;
    int d = (e < NEDGE) ? ei[NEDGE + e] : (e - NEDGE);
    atomicAdd(&g_cnt[d], 1);
}
__global__ void k_scan() {
    __shared__ int sh[1024];
    int t = threadIdx.x;
    const int CH = (NNODE + 1023) / 1024;
    int base = t * CH;
    int s = 0;
    for (int i = 0; i < CH; i++) {
        int idx = base + i;
        if (idx < NNODE) s += g_cnt[idx];
    }
    sh[t] = s;
    __syncthreads();
    for (int off = 1; off < 1024; off <<= 1) {
        int v = (t >= off) ? sh[t - off] : 0;
        __syncthreads();
        sh[t] += v;
        __syncthreads();
    }
    int run = (t == 0) ? 0 : sh[t - 1];
    for (int i = 0; i < CH; i++) {
        int idx = base + i;
        if (idx < NNODE) {
            g_offs[idx]   = run;
            g_cursor[idx] = run;
            run += g_cnt[idx];
        }
    }
    if (t == 1023) g_offs[NNODE] = run;
}
__global__ void k_scatter(const int* __restrict__ ei, const float* __restrict__ ew) {
    int e = blockIdx.x * blockDim.x + threadIdx.x;
    if (e >= ETOT) return;
    int s, d; float lw;
    if (e < NEDGE) {
        s = ei[e]; d = ei[NEDGE + e];
        lw = log2f(ew[e]);
    } else {
        s = d = e - NEDGE;
        lw = 0.f;
    }
    int pos = atomicAdd(&g_cursor[d], 1);
    g_edge[pos] = make_int2(s, __float_as_int(lw));
}

// ---------------- 3xBF16 tensor-core GEMM + fused att-dot epilogue ----------
// 64x128 CTA tile (2 CTAs/SM), BK=16, coalesced fp32 loads, in-register
// hi/lo split, mma.m16n8k16.bf16 x3 products, double-buffered smem.
__device__ __forceinline__ uint32_t bf16x2(float odd, float even) {
    uint32_t r;
    asm("cvt.rn.bf16x2.f32 %0, %1, %2;" : "=r"(r) : "f"(odd), "f"(even));
    return r;
}
__device__ __forceinline__ void split2(float even, float odd,
                                       uint32_t& H, uint32_t& L) {
    H = bf16x2(odd, even);
    float eh = __uint_as_float(H << 16);
    float oh = __uint_as_float(H & 0xffff0000u);
    L = bf16x2(odd - oh, even - eh);
}
__device__ __forceinline__ void mma_bf16(float c[4],
                                         uint32_t a0, uint32_t a1, uint32_t a2, uint32_t a3,
                                         uint32_t b0, uint32_t b1) {
    asm volatile(
        "mma.sync.aligned.m16n8k16.row.col.f32.bf16.bf16.f32 "
        "{%0,%1,%2,%3}, {%4,%5,%6,%7}, {%8,%9}, {%0,%1,%2,%3};"
        : "+f"(c[0]), "+f"(c[1]), "+f"(c[2]), "+f"(c[3])
        : "r"(a0), "r"(a1), "r"(a2), "r"(a3), "r"(b0), "r"(b1));
}

#define APITCH 72    /* 72 mod 32 = 8 -> conflict-free A frag LDS */
#define BPITCH 136   /* 136 mod 32 = 8 -> conflict-free B frag LDS */

__global__ __launch_bounds__(256, 2) void k_gemm_tc(
    const float* __restrict__ A_ext, const float* __restrict__ B,
    const float* __restrict__ att_s, const float* __restrict__ att_d,
    int M, int K, int layer)
{
    __shared__ uint32_t AsH[2][8][APITCH];
    __shared__ uint32_t AsL[2][8][APITCH];
    __shared__ uint32_t BsH[2][8][BPITCH];
    __shared__ uint32_t BsL[2][8][BPITCH];

    const float* A = layer ? g_x2 : A_ext;
    float* als = g_als[layer];
    float* ald = g_ald[layer];
    const int NN = FOUT;

    int bm = blockIdx.y * 64;
    int bn = blockIdx.x * 128;
    int tid  = threadIdx.x;
    int lane = tid & 31;
    int warp = tid >> 5;
    int wm = (warp & 1) * 32;    // warp row offset (2 warp-rows)
    int wn = (warp >> 1) * 32;   // warp col offset (4 warp-cols)

    // A tile 64x16 fp32: row = tid>>2, k offset = (tid&3)*4 (one float4)
    int am = tid >> 2;
    int ak = (tid & 3) * 4;
    int arow = bm + am;
    // B tile 16x128 fp32: kpair row = tid>>5, cols (tid&31)*4
    int br = tid >> 5;
    int bc = (tid & 31) * 4;

    float acc[2][4][4];
#pragma unroll
    for (int mi = 0; mi < 2; mi++)
#pragma unroll
        for (int ni = 0; ni < 4; ni++)
#pragma unroll
            for (int r = 0; r < 4; r++) acc[mi][ni][r] = 0.f;

    float4 av, b0v, b1v;
    auto load_tile = [&](int k0) {
        av = (arow < M) ? *(const float4*)(A + (size_t)arow * K + k0 + ak)
                        : make_float4(0.f, 0.f, 0.f, 0.f);
        b0v = *(const float4*)(B + (size_t)(k0 + 2 * br) * NN + bn + bc);
        b1v = *(const float4*)(B + (size_t)(k0 + 2 * br + 1) * NN + bn + bc);
    };
    auto store_tile = [&](int buf) {
        int akp = ak >> 1;   // kpair base: 0,2,4,6
        uint32_t H0, L0, H1, L1;
        split2(av.x, av.y, H0, L0);
        split2(av.z, av.w, H1, L1);
        AsH[buf][akp][am]     = H0;  AsL[buf][akp][am]     = L0;
        AsH[buf][akp + 1][am] = H1;  AsL[buf][akp + 1][am] = L1;
        float ve[4] = {b0v.x, b0v.y, b0v.z, b0v.w};
        float vo[4] = {b1v.x, b1v.y, b1v.z, b1v.w};
        uint32_t BH[4], BL[4];
#pragma unroll
        for (int j = 0; j < 4; j++) split2(ve[j], vo[j], BH[j], BL[j]);
        *(uint4*)&BsH[buf][br][bc] = make_uint4(BH[0], BH[1], BH[2], BH[3]);
        *(uint4*)&BsL[buf][br][bc] = make_uint4(BL[0], BL[1], BL[2], BL[3]);
    };

    load_tile(0);
    store_tile(0);
    __syncthreads();

    int buf = 0;
    for (int k0 = 0; k0 < K; k0 += 16) {
        bool has_next = (k0 + 16) < K;
        if (has_next) load_tile(k0 + 16);

        int fk = lane & 3;
        int fg = lane >> 2;
        uint32_t ah[2][4], al[2][4];
#pragma unroll
        for (int mi = 0; mi < 2; mi++) {
            int m0 = wm + mi * 16 + fg;
            ah[mi][0] = AsH[buf][fk][m0];      ah[mi][1] = AsH[buf][fk][m0 + 8];
            ah[mi][2] = AsH[buf][fk + 4][m0];  ah[mi][3] = AsH[buf][fk + 4][m0 + 8];
            al[mi][0] = AsL[buf][fk][m0];      al[mi][1] = AsL[buf][fk][m0 + 8];
            al[mi][2] = AsL[buf][fk + 4][m0];  al[mi][3] = AsL[buf][fk + 4][m0 + 8];
        }
        uint32_t bh[4][2], bl[4][2];
#pragma unroll
        for (int ni = 0; ni < 4; ni++) {
            int n0 = wn + ni * 8 + fg;
            bh[ni][0] = BsH[buf][fk][n0];      bh[ni][1] = BsH[buf][fk + 4][n0];
            bl[ni][0] = BsL[buf][fk][n0];      bl[ni][1] = BsL[buf][fk + 4][n0];
        }

#pragma unroll
        for (int mi = 0; mi < 2; mi++)
#pragma unroll
            for (int ni = 0; ni < 4; ni++) {
                mma_bf16(acc[mi][ni], ah[mi][0], ah[mi][1], ah[mi][2], ah[mi][3],
                         bh[ni][0], bh[ni][1]);
                mma_bf16(acc[mi][ni], ah[mi][0], ah[mi][1], ah[mi][2], ah[mi][3],
                         bl[ni][0], bl[ni][1]);
                mma_bf16(acc[mi][ni], al[mi][0], al[mi][1], al[mi][2], al[mi][3],
                         bh[ni][0], bh[ni][1]);
            }

        if (has_next) store_tile(buf ^ 1);
        __syncthreads();
        buf ^= 1;
    }

    // ---- epilogue: fp16 store + fused att dot products ----
    int fg = lane >> 2;
    int fk = lane & 3;
    int headg = (bn + wn) >> 6;

    float vsv[4][2], vdv[4][2];
#pragma unroll
    for (int ni = 0; ni < 4; ni++) {
        int c = bn + wn + ni * 8 + fk * 2;
        vsv[ni][0] = att_s[c]; vsv[ni][1] = att_s[c + 1];
        vdv[ni][0] = att_d[c]; vdv[ni][1] = att_d[c + 1];
    }

#pragma unroll
    for (int mi = 0; mi < 2; mi++) {
        int r0 = bm + wm + mi * 16 + fg;
        int r1 = r0 + 8;
        float s0 = 0.f, d0 = 0.f, s1 = 0.f, d1 = 0.f;
#pragma unroll
        for (int ni = 0; ni < 4; ni++) {
            int col = bn + wn + ni * 8 + fk * 2;
            __half2 h01 = __floats2half2_rn(acc[mi][ni][0], acc[mi][ni][1]);
            __half2 h23 = __floats2half2_rn(acc[mi][ni][2], acc[mi][ni][3]);
            if (r0 < M) *(__half2*)(g_hh + (size_t)r0 * NN + col) = h01;
            if (r1 < M) *(__half2*)(g_hh + (size_t)r1 * NN + col) = h23;
            s0 += acc[mi][ni][0] * vsv[ni][0] + acc[mi][ni][1] * vsv[ni][1];
            d0 += acc[mi][ni][0] * vdv[ni][0] + acc[mi][ni][1] * vdv[ni][1];
            s1 += acc[mi][ni][2] * vsv[ni][0] + acc[mi][ni][3] * vsv[ni][1];
            d1 += acc[mi][ni][2] * vdv[ni][0] + acc[mi][ni][3] * vdv[ni][1];
        }
#pragma unroll
        for (int off = 2; off; off >>= 1) {
            s0 += __shfl_xor_sync(0xffffffffu, s0, off);
            d0 += __shfl_xor_sync(0xffffffffu, d0, off);
            s1 += __shfl_xor_sync(0xffffffffu, s1, off);
            d1 += __shfl_xor_sync(0xffffffffu, d1, off);
        }
        if (fk == 0) {
            if (r0 < M) {
                atomicAdd(&als[r0 * HH + headg], s0);
                atomicAdd(&ald[r0 * HH + headg], d0);
            }
            if (r1 < M) {
                atomicAdd(&als[r1 * HH + headg], s1);
                atomicAdd(&ald[r1 * HH + headg], d1);
            }
        }
    }
}

// ------------- fused flash softmax + aggregation: warp = (node, head) -------
__global__ void k_fusedagg(const float* __restrict__ bias,
                           float* __restrict__ out_ext, int do_relu, int layer)
{
    int n = blockIdx.x;
    int w = threadIdx.x >> 5, lane = threadIdx.x & 31;
    float* out = out_ext ? out_ext : g_x2;
    const float* als = g_als[layer];
    int s0 = g_offs[n], s1 = g_offs[n + 1];

    float adw = g_ald[layer][n * HH + w];
    float m = -1e30f, ssum = 0.f, accx = 0.f, accy = 0.f;

    for (int base = s0; base < s1; base += 32) {
        int idx = base + lane;
        bool valid = idx < s1;
        int2 e2 = valid ? g_edge[idx] : make_int2(0, 0);
        int mys = e2.x;
        float t = -1e30f;
        if (valid) {
            float a = als[mys * HH + w] + adw;
            a = (a > 0.f) ? a : NEG * a;   // leaky_relu
            t = a + __int_as_float(e2.y);
        }
        float cm = t;
#pragma unroll
        for (int o = 16; o; o >>= 1)
            cm = fmaxf(cm, __shfl_xor_sync(0xffffffffu, cm, o));
        float mnew = fmaxf(m, cm);
        float scale = __expf(m - mnew);
        ssum *= scale; accx *= scale; accy *= scale;
        m = mnew;

        float e = __expf(t - mnew);   // exactly 0 for invalid lanes
        ssum += e;

        int cnt = min(32, s1 - base);
        const __half* hrow_base = g_hh + w * CC + lane * 2;
        for (int jb = 0; jb < cnt; jb += 8) {
            float wv[8];
            float2 hv[8];
#pragma unroll
            for (int u = 0; u < 8; u++) {
                int j = (jb + u) & 31;
                int   s  = __shfl_sync(0xffffffffu, mys, j);
                wv[u]    = __shfl_sync(0xffffffffu, e, j);
                hv[u] = __half22float2(
                    *(const __half2*)(hrow_base + (size_t)s * FOUT));
            }
#pragma unroll
            for (int u = 0; u < 8; u++) {
                accx = fmaf(wv[u], hv[u].x, accx);
                accy = fmaf(wv[u], hv[u].y, accy);
            }
        }
    }
#pragma unroll
    for (int o = 16; o; o >>= 1)
        ssum += __shfl_xor_sync(0xffffffffu, ssum, o);

    float r = 1.f / ssum;
    float2 b = *(const float2*)(bias + w * CC + lane * 2);
    float ox = fmaf(accx, r, b.x);
    float oy = fmaf(accy, r, b.y);
    if (do_relu) { ox = fmaxf(ox, 0.f); oy = fmaxf(oy, 0.f); }
    *(float2*)(out + (size_t)n * FOUT + w * CC + lane * 2) = make_float2(ox, oy);
}

// ---------------- launch -----------------------------------------------------
extern "C" void kernel_launch(void* const* d_in, const int* in_sizes, int n_in,
                              void* d_out, int out_size)
{
    const float* x   = (const float*)d_in[0];
    const int*   ei  = (const int*)  d_in[1];
    const float* ew  = (const float*)d_in[2];
    const float* W1  = (const float*)d_in[3];
    const float* as1 = (const float*)d_in[4];
    const float* ad1 = (const float*)d_in[5];
    const float* b1  = (const float*)d_in[6];
    const float* W2  = (const float*)d_in[7];
    const float* as2 = (const float*)d_in[8];
    const float* ad2 = (const float*)d_in[9];
    const float* b2  = (const float*)d_in[10];
    float* out = (float*)d_out;

    // fork: CSR build chain runs concurrently with layer-1 GEMM.
    // (stream/event creation is host-side only — no device allocations)
    cudaStream_t s2;
    cudaStreamCreateWithFlags(&s2, cudaStreamNonBlocking);
    cudaEvent_t evFork, evCsr;
    cudaEventCreateWithFlags(&evFork, cudaEventDisableTiming);
    cudaEventCreateWithFlags(&evCsr, cudaEventDisableTiming);

    cudaEventRecord(evFork, 0);
    cudaStreamWaitEvent(s2, evFork, 0);
    k_zero_cnt<<<(NNODE + 255) / 256, 256, 0, s2>>>();
    k_hist<<<(ETOT + 255) / 256, 256, 0, s2>>>(ei);
    k_scan<<<1, 1024, 0, s2>>>();
    k_scatter<<<(ETOT + 255) / 256, 256, 0, s2>>>(ei, ew);
    cudaEventRecord(evCsr, s2);

    dim3 ggrid(FOUT / 128, (NNODE + 63) / 64);

    // main stream: zero att accumulators, then layer-1 GEMM (independent of CSR)
    k_zero_att<<<(NNODE * HH + 255) / 256, 256>>>();
    k_gemm_tc<<<ggrid, 256>>>(x, W1, as1, ad1, NNODE, FIN, 0);

    // join: aggregation needs the CSR
    cudaStreamWaitEvent(0, evCsr, 0);
    k_fusedagg<<<NNODE, 256>>>(b1, nullptr, 1, 0);    // -> g_x2 with ReLU

    // layer 2
    k_gemm_tc<<<ggrid, 256>>>(nullptr, W2, as2, ad2, NNODE, FOUT, 1);
    k_fusedagg<<<NNODE, 256>>>(b2, out, 0, 1);        // -> d_out, no ReLU
}